// round 9
// baseline (speedup 1.0000x reference)
#include <cuda_runtime.h>
#include <stdint.h>

// Problem constants
#define NT    256      // threads per CTA (4 groups x 64 channels)
#define NBSUB 4        // b-values per thread
#define NB    16       // b-values per CTA
#define DIM   40
#define NPAIR 820      // DIM*(DIM+1)/2 unique symmetric pairs
#define NROWS 860      // pairs + 40 U1 rows
#define TS    16       // table row stride (floats)
#define XROWB 4096     // x row stride in bytes (256 threads * 16B)

// Packed coefficient table, ROW-MAJOR TRIANGULAR order (i outer, j from i):
//  rows [0,820): per pair (i<=j): 13 symmetric-folded U2 coeffs (off-diag doubled), 3 pad
//  rows [820,860): per i: 13 U1 coeffs, 3 pad
__device__ float g_table[NROWS * TS];

__global__ void prep_kernel(const float* __restrict__ U2_0,
                            const float* __restrict__ U1_0,
                            const float* __restrict__ U2_1,
                            const float* __restrict__ U1_1,
                            const float* __restrict__ U2_2,
                            const float* __restrict__ U1_2) {
    int idx = blockIdx.x * blockDim.x + threadIdx.x;
    if (idx >= NROWS) return;
    float row[TS];
#pragma unroll
    for (int k = 0; k < TS; k++) row[k] = 0.0f;

    if (idx < NPAIR) {
        // invert p -> (i, j) for row-major triangular order (i outer, j from i)
        int rem = idx;
        int i = 0;
        while (rem >= DIM - i) { rem -= DIM - i; i++; }
        int j = i + rem;
        const float* U2b[3] = {U2_0, U2_1, U2_2};
#pragma unroll
        for (int m = 0; m < 13; m++) {
            int l  = (m == 0) ? 0 : ((m < 4) ? 1 : 2);
            int mm = (m == 0) ? 0 : ((m < 4) ? (m - 1) : (m - 4));
            const float* U = U2b[l];
            float v = U[(mm * DIM + i) * DIM + j];
            if (i != j) v += U[(mm * DIM + j) * DIM + i];
            row[m] = v;
        }
    } else {
        int i = idx - NPAIR;
        const float* U1b[3] = {U1_0, U1_1, U1_2};
#pragma unroll
        for (int m = 0; m < 13; m++) {
            int l  = (m == 0) ? 0 : ((m < 4) ? 1 : 2);
            int mm = (m == 0) ? 0 : ((m < 4) ? (m - 1) : (m - 4));
            row[m] = U1b[l][mm * DIM + i];
        }
    }
#pragma unroll
    for (int k = 0; k < TS; k++) g_table[idx * TS + k] = row[k];
}

// ---- packed f32x2 helpers ----
__device__ __forceinline__ void fma2(unsigned long long& acc,
                                     unsigned long long u,
                                     unsigned long long y) {
    asm("fma.rn.f32x2 %0, %1, %2, %0;" : "+l"(acc) : "l"(u), "l"(y));
}
__device__ __forceinline__ unsigned long long dup2(float y) {
    unsigned long long r;
    asm("mov.b64 %0, {%1, %1};" : "=l"(r) : "f"(y));
    return r;
}
__device__ __forceinline__ float2 unpk2(unsigned long long v) {
    float2 r;
    asm("mov.b64 {%0, %1}, %2;" : "=f"(r.x), "=f"(r.y) : "l"(v));
    return r;
}

// SMEM layout (floats):
//   region0 [0, 13312):     pair table (13120 used) -> after phase A becomes
//                           basis13[16 b][64 c][13 m] (13312)
//   xS      [13312, 54272): x[40][256 threads][4 b] (160 KB) -> after phase B:
//                           Wlin (12288) at 13312, basis20 (20480) at 25600
//   u1S     [54272, 54912): U1 rows (40 x 16)
#define REG0_F   13312
#define XS_OFF   13312
#define U1_OFF   54272
#define SMEM_FLOATS 54912
#define SMEM_BYTES  (SMEM_FLOATS * 4)
#define BSTRIDE 20     // final basis row stride in floats

__global__ __launch_bounds__(NT, 1)
void main_kernel(const float* __restrict__ f0,  const float* __restrict__ f1,
                 const float* __restrict__ f2,  const float* __restrict__ f3,
                 const float* __restrict__ attrs,
                 const float* __restrict__ W1_0, const float* __restrict__ W2_0,
                 const float* __restrict__ Wl0,  const float* __restrict__ sc0,
                 const float* __restrict__ W1_1, const float* __restrict__ W2_1,
                 const float* __restrict__ Wl1,  const float* __restrict__ sc1,
                 const float* __restrict__ W1_2, const float* __restrict__ W2_2,
                 const float* __restrict__ Wl2,  const float* __restrict__ sc2,
                 float* __restrict__ out, int B) {
    extern __shared__ float S[];
    float* tabS = S;                // pair table, later basis13
    float* xS   = S + XS_OFF;       // x, later Wlin + basis20
    float* u1S  = S + U1_OFF;       // U1 rows

    const int tid = threadIdx.x;
    const int g   = tid >> 6;        // b-group 0..3
    const int c   = tid & 63;        // channel
    const int b0  = blockIdx.x * NB + g * NBSUB;

    // cooperative copy: pair rows -> tabS, U1 rows -> u1S
    {
        const float4* gt4 = (const float4*)g_table;
        float4* tp4 = (float4*)tabS;
#pragma unroll
        for (int k = 0; k < 13; k++) {
            int idx = k * NT + tid;
            if (idx < NPAIR * TS / 4) tp4[idx] = gt4[idx];
        }
        float4* up4 = (float4*)u1S;
        if (tid < 160) up4[tid] = gt4[NPAIR * 4 + tid];
    }

    // gather x for 4 b's: xS[i*1024 + tid*4 + s]
#pragma unroll
    for (int s = 0; s < NBSUB; s++) {
        int bb = b0 + s; if (bb >= B) bb = B - 1;
        const int base = bb * 64 + c;
        xS[tid * 4 + s] = f0[base];
#pragma unroll
        for (int k = 0; k < 3; k++)
            xS[(1 + k) * 1024 + tid * 4 + s]  = f1[base * 3 + k];
#pragma unroll
        for (int k = 0; k < 9; k++)
            xS[(4 + k) * 1024 + tid * 4 + s]  = f2[base * 9 + k];
#pragma unroll
        for (int k = 0; k < 27; k++)
            xS[(13 + k) * 1024 + tid * 4 + s] = f3[base * 27 + k];
    }
    __syncthreads();

    const char* xtb = (const char*)xS + tid * 16;
    const int LSEL[14] = {0, 1, 1, 1, 2, 2, 2, 2, 2, 2, 2, 2, 2, 0};

    // ---- phase A: a2[s][m] = sum_{i<=j} u[p][m] * x_i[s] * x_j[s] ----
    {
        unsigned long long a2[NBSUB][7];
#pragma unroll
        for (int s = 0; s < NBSUB; s++)
#pragma unroll
            for (int k = 0; k < 7; k++) a2[s][k] = 0ull;

        const ulonglong2* trow = (const ulonglong2*)tabS;
        for (int i = 0; i < DIM; i++) {
            const float4 xi = *(const float4*)(xtb + i * XROWB);
            const char* xjp = xtb + i * XROWB;
#pragma unroll 2
            for (int j = i; j < DIM; j++) {
                ulonglong2 q0 = trow[0];
                ulonglong2 q1 = trow[1];
                ulonglong2 q2 = trow[2];
                ulonglong2 q3 = trow[3];
                trow += 4;
                float4 xj = *(const float4*)xjp;
                xjp += XROWB;
                unsigned long long y0 = dup2(xi.x * xj.x);
                unsigned long long y1 = dup2(xi.y * xj.y);
                unsigned long long y2 = dup2(xi.z * xj.z);
                unsigned long long y3 = dup2(xi.w * xj.w);
                fma2(a2[0][0], q0.x, y0); fma2(a2[1][0], q0.x, y1);
                fma2(a2[2][0], q0.x, y2); fma2(a2[3][0], q0.x, y3);
                fma2(a2[0][1], q0.y, y0); fma2(a2[1][1], q0.y, y1);
                fma2(a2[2][1], q0.y, y2); fma2(a2[3][1], q0.y, y3);
                fma2(a2[0][2], q1.x, y0); fma2(a2[1][2], q1.x, y1);
                fma2(a2[2][2], q1.x, y2); fma2(a2[3][2], q1.x, y3);
                fma2(a2[0][3], q1.y, y0); fma2(a2[1][3], q1.y, y1);
                fma2(a2[2][3], q1.y, y2); fma2(a2[3][3], q1.y, y3);
                fma2(a2[0][4], q2.x, y0); fma2(a2[1][4], q2.x, y1);
                fma2(a2[2][4], q2.x, y2); fma2(a2[3][4], q2.x, y3);
                fma2(a2[0][5], q2.y, y0); fma2(a2[1][5], q2.y, y1);
                fma2(a2[2][5], q2.y, y2); fma2(a2[3][5], q2.y, y3);
                fma2(a2[0][6], q3.x, y0); fma2(a2[1][6], q3.x, y1);
                fma2(a2[2][6], q3.x, y2); fma2(a2[3][6], q3.x, y3);
            }
        }

        __syncthreads();   // all warps done reading pair table

        // element-aware nu=2 weights, then fold a2*w2 -> basis13 (table region)
#pragma unroll
        for (int s = 0; s < NBSUB; s++) {
            int bb = b0 + s; if (bb >= B) bb = B - 1;
            float a20 = 0.f, a21 = 0.f, a22v = 0.f;
#pragma unroll
            for (int e = 0; e < 10; e++) {
                float a = __ldg(&attrs[bb * 10 + e]);
                a20  += a * __ldg(&W2_0[e * 64 + c]);
                a21  += a * __ldg(&W2_1[e * 64 + c]);
                a22v += a * __ldg(&W2_2[e * 64 + c]);
            }
            float w2v[3] = {a20, a21, a22v};
            float* b13 = tabS + ((g * NBSUB + s) * 64 + c) * 13;
#pragma unroll
            for (int k = 0; k < 7; k++) {
                float2 v = unpk2(a2[s][k]);
                int m0 = 2 * k, m1 = 2 * k + 1;
                b13[m0] = v.x * w2v[LSEL[m0]];
                if (m1 < 13) b13[m1] = v.y * w2v[LSEL[m1]];
            }
        }
    }

    // ---- phase B: a1[s][m] = U1[m,:] . x[s]  (reads u1S + xS) ----
    unsigned long long a1[NBSUB][7];
#pragma unroll
    for (int s = 0; s < NBSUB; s++)
#pragma unroll
        for (int k = 0; k < 7; k++) a1[s][k] = 0ull;

    {
        const ulonglong2* urow = (const ulonglong2*)u1S;
#pragma unroll 2
        for (int i = 0; i < DIM; i++, urow += 4) {
            ulonglong2 q0 = urow[0];
            ulonglong2 q1 = urow[1];
            ulonglong2 q2 = urow[2];
            ulonglong2 q3 = urow[3];
            float4 xi = *(const float4*)(xtb + i * XROWB);
            unsigned long long y0 = dup2(xi.x);
            unsigned long long y1 = dup2(xi.y);
            unsigned long long y2 = dup2(xi.z);
            unsigned long long y3 = dup2(xi.w);
            fma2(a1[0][0], q0.x, y0); fma2(a1[1][0], q0.x, y1);
            fma2(a1[2][0], q0.x, y2); fma2(a1[3][0], q0.x, y3);
            fma2(a1[0][1], q0.y, y0); fma2(a1[1][1], q0.y, y1);
            fma2(a1[2][1], q0.y, y2); fma2(a1[3][1], q0.y, y3);
            fma2(a1[0][2], q1.x, y0); fma2(a1[1][2], q1.x, y1);
            fma2(a1[2][2], q1.x, y2); fma2(a1[3][2], q1.x, y3);
            fma2(a1[0][3], q1.y, y0); fma2(a1[1][3], q1.y, y1);
            fma2(a1[2][3], q1.y, y2); fma2(a1[3][3], q1.y, y3);
            fma2(a1[0][4], q2.x, y0); fma2(a1[1][4], q2.x, y1);
            fma2(a1[2][4], q2.x, y2); fma2(a1[3][4], q2.x, y3);
            fma2(a1[0][5], q2.y, y0); fma2(a1[1][5], q2.y, y1);
            fma2(a1[2][5], q2.y, y2); fma2(a1[3][5], q2.y, y3);
            fma2(a1[0][6], q3.x, y0); fma2(a1[1][6], q3.x, y1);
            fma2(a1[2][6], q3.x, y2); fma2(a1[3][6], q3.x, y3);
        }
    }

    __syncthreads();   // everyone done reading xS before we overwrite it

    // xS region reuse: Wlin cache + aligned basis20
    float* wlS    = xS;             // 12288 floats
    float* basS20 = xS + 12288;     // 20480 floats

    // Wlin cache: wlS[l*4096 + cc*64 + o]
    {
        const float4* a0p = (const float4*)Wl0;
        const float4* a1p = (const float4*)Wl1;
        const float4* a2p = (const float4*)Wl2;
        float4* w4 = (float4*)wlS;
#pragma unroll
        for (int k = 0; k < 4; k++) {
            int idx = k * NT + tid;
            w4[idx]        = a0p[idx];
            w4[1024 + idx] = a1p[idx];
            w4[2048 + idx] = a2p[idx];
        }
    }

    // nu=1 weights, then basis20 = basis13 + a1*w1
#pragma unroll
    for (int s = 0; s < NBSUB; s++) {
        int bb = b0 + s; if (bb >= B) bb = B - 1;
        float a10 = 0.f, a11 = 0.f, a12v = 0.f;
#pragma unroll
        for (int e = 0; e < 10; e++) {
            float a = __ldg(&attrs[bb * 10 + e]);
            a10  += a * __ldg(&W1_0[e * 64 + c]);
            a11  += a * __ldg(&W1_1[e * 64 + c]);
            a12v += a * __ldg(&W1_2[e * 64 + c]);
        }
        float w1v[3] = {a10, a11, a12v};
        const int row = (g * NBSUB + s) * 64 + c;
        const float* b13 = tabS + row * 13;
        float* b20 = basS20 + row * BSTRIDE;
#pragma unroll
        for (int k = 0; k < 7; k++) {
            float2 v = unpk2(a1[s][k]);
            int m0 = 2 * k, m1 = 2 * k + 1;
            b20[m0] = b13[m0] + v.x * w1v[LSEL[m0]];
            if (m1 < 13) b20[m1] = b13[m1] + v.y * w1v[LSEL[m1]];
        }
    }
    __syncthreads();

    // ---- self-interaction: r[s][m] = sum_cc basis[b_s][cc][m] * Wlin_l[cc][c] ----
    float r[NBSUB][13];
#pragma unroll
    for (int s = 0; s < NBSUB; s++)
#pragma unroll
        for (int m = 0; m < 13; m++) r[s][m] = 0.0f;

#pragma unroll 2
    for (int cc = 0; cc < 64; cc++) {
        float wv0 = wlS[cc * 64 + c];
        float wv1 = wlS[4096 + cc * 64 + c];
        float wv2 = wlS[8192 + cc * 64 + c];
#pragma unroll
        for (int s = 0; s < NBSUB; s++) {
            const float* br = basS20 + ((g * NBSUB + s) * 64 + cc) * BSTRIDE;
            float4 q0 = *(const float4*)(br);
            float4 q1 = *(const float4*)(br + 4);
            float4 q2 = *(const float4*)(br + 8);
            float b12 = br[12];
            r[s][0]  += q0.x * wv0;
            r[s][1]  += q0.y * wv1;
            r[s][2]  += q0.z * wv1;
            r[s][3]  += q0.w * wv1;
            r[s][4]  += q1.x * wv2;
            r[s][5]  += q1.y * wv2;
            r[s][6]  += q1.z * wv2;
            r[s][7]  += q1.w * wv2;
            r[s][8]  += q2.x * wv2;
            r[s][9]  += q2.y * wv2;
            r[s][10] += q2.z * wv2;
            r[s][11] += q2.w * wv2;
            r[s][12] += b12  * wv2;
        }
    }

    // ---- outputs: concat [out0 (B,C)] [out1 (B,C,3)] [out2 (B,C,9)] ----
    float* o0 = out;
    float* o1 = out + (size_t)B * 64;
    float* o2 = out + (size_t)B * 64 * 4;
#pragma unroll
    for (int s = 0; s < NBSUB; s++) {
        int bb = b0 + s;
        if (bb >= B) break;
        const int bo = bb * 64 + c;
        o0[bo] = r[s][0] + __ldg(&sc0[bo]);
#pragma unroll
        for (int k = 0; k < 3; k++)
            o1[bo * 3 + k] = r[s][1 + k] + __ldg(&sc1[bo * 3 + k]);
#pragma unroll
        for (int k = 0; k < 9; k++)
            o2[bo * 9 + k] = r[s][4 + k] + __ldg(&sc2[bo * 9 + k]);
    }
}

extern "C" void kernel_launch(void* const* d_in, const int* in_sizes, int n_in,
                              void* d_out, int out_size) {
    const float* f0    = (const float*)d_in[0];
    const float* f1    = (const float*)d_in[1];
    const float* f2    = (const float*)d_in[2];
    const float* f3    = (const float*)d_in[3];
    const float* attrs = (const float*)d_in[4];
    const float* U2_0  = (const float*)d_in[5];
    const float* U1_0  = (const float*)d_in[6];
    const float* W1_0  = (const float*)d_in[7];
    const float* W2_0  = (const float*)d_in[8];
    const float* Wl0   = (const float*)d_in[9];
    const float* sc0   = (const float*)d_in[10];
    const float* U2_1  = (const float*)d_in[11];
    const float* U1_1  = (const float*)d_in[12];
    const float* W1_1  = (const float*)d_in[13];
    const float* W2_1  = (const float*)d_in[14];
    const float* Wl1   = (const float*)d_in[15];
    const float* sc1   = (const float*)d_in[16];
    const float* U2_2  = (const float*)d_in[17];
    const float* U1_2  = (const float*)d_in[18];
    const float* W1_2  = (const float*)d_in[19];
    const float* W2_2  = (const float*)d_in[20];
    const float* Wl2   = (const float*)d_in[21];
    const float* sc2   = (const float*)d_in[22];

    const int B = in_sizes[0] / 64;

    cudaFuncSetAttribute(main_kernel,
                         cudaFuncAttributeMaxDynamicSharedMemorySize, SMEM_BYTES);

    prep_kernel<<<(NROWS + 255) / 256, 256>>>(U2_0, U1_0, U2_1, U1_1, U2_2, U1_2);

    const int grid = (B + NB - 1) / NB;
    main_kernel<<<grid, NT, SMEM_BYTES>>>(f0, f1, f2, f3, attrs,
                                          W1_0, W2_0, Wl0, sc0,
                                          W1_1, W2_1, Wl1, sc1,
                                          W1_2, W2_2, Wl2, sc2,
                                          (float*)d_out, B);
}

// round 10
// speedup vs baseline: 1.5097x; 1.5097x over previous
#include <cuda_runtime.h>
#include <stdint.h>

// Problem constants
#define NT    256      // threads per CTA (4 groups x 64 channels)
#define NBSUB 4        // b-values per thread
#define NB    16       // b-values per CTA
#define DIM   40
#define NPAIR 820      // DIM*(DIM+1)/2 unique symmetric pairs
#define NROWS 860      // pairs + 40 U1 rows
#define TS    16       // table row stride (floats)
#define XROWB 4096     // x row stride in bytes (256 threads * 16B)

// Packed coefficient table, ROW-MAJOR TRIANGULAR order (i outer, j from i):
//  rows [0,820): per pair (i<=j): 13 symmetric-folded U2 coeffs (off-diag doubled), 3 pad
//  rows [820,860): per i: 13 U1 coeffs, 3 pad
__device__ float g_table[NROWS * TS];

__global__ void prep_kernel(const float* __restrict__ U2_0,
                            const float* __restrict__ U1_0,
                            const float* __restrict__ U2_1,
                            const float* __restrict__ U1_1,
                            const float* __restrict__ U2_2,
                            const float* __restrict__ U1_2) {
    int idx = blockIdx.x * blockDim.x + threadIdx.x;
    if (idx >= NROWS) return;
    float row[TS];
#pragma unroll
    for (int k = 0; k < TS; k++) row[k] = 0.0f;

    if (idx < NPAIR) {
        // invert p -> (i, j) for row-major triangular order (i outer, j from i)
        int rem = idx;
        int i = 0;
        while (rem >= DIM - i) { rem -= DIM - i; i++; }
        int j = i + rem;
        const float* U2b[3] = {U2_0, U2_1, U2_2};
#pragma unroll
        for (int m = 0; m < 13; m++) {
            int l  = (m == 0) ? 0 : ((m < 4) ? 1 : 2);
            int mm = (m == 0) ? 0 : ((m < 4) ? (m - 1) : (m - 4));
            const float* U = U2b[l];
            float v = U[(mm * DIM + i) * DIM + j];
            if (i != j) v += U[(mm * DIM + j) * DIM + i];
            row[m] = v;
        }
    } else {
        int i = idx - NPAIR;
        const float* U1b[3] = {U1_0, U1_1, U1_2};
#pragma unroll
        for (int m = 0; m < 13; m++) {
            int l  = (m == 0) ? 0 : ((m < 4) ? 1 : 2);
            int mm = (m == 0) ? 0 : ((m < 4) ? (m - 1) : (m - 4));
            row[m] = U1b[l][mm * DIM + i];
        }
    }
#pragma unroll
    for (int k = 0; k < TS; k++) g_table[idx * TS + k] = row[k];
}

// ---- packed f32x2 helpers ----
__device__ __forceinline__ void fma2(unsigned long long& acc,
                                     unsigned long long u,
                                     unsigned long long y) {
    asm("fma.rn.f32x2 %0, %1, %2, %0;" : "+l"(acc) : "l"(u), "l"(y));
}
__device__ __forceinline__ unsigned long long dup2(float y) {
    unsigned long long r;
    asm("mov.b64 %0, {%1, %1};" : "=l"(r) : "f"(y));
    return r;
}
__device__ __forceinline__ float2 unpk2(unsigned long long v) {
    float2 r;
    asm("mov.b64 {%0, %1}, %2;" : "=f"(r.x), "=f"(r.y) : "l"(v));
    return r;
}

// SMEM layout (floats):
//   [0,     13760)  coeff table (55 KB)
//   [13760, 54720)  xS: x[40][256 threads][4 b]  (160 KB)
//                   reused after phases: Wlin (12288) + basis20 (20480)
#define SMEM_FLOATS 54720
#define SMEM_BYTES  (SMEM_FLOATS * 4)
#define BSTRIDE 20     // basis row stride in floats

__global__ __launch_bounds__(NT, 1)
void main_kernel(const float* __restrict__ f0,  const float* __restrict__ f1,
                 const float* __restrict__ f2,  const float* __restrict__ f3,
                 const float* __restrict__ attrs,
                 const float* __restrict__ W1_0, const float* __restrict__ W2_0,
                 const float* __restrict__ Wl0,  const float* __restrict__ sc0,
                 const float* __restrict__ W1_1, const float* __restrict__ W2_1,
                 const float* __restrict__ Wl1,  const float* __restrict__ sc1,
                 const float* __restrict__ W1_2, const float* __restrict__ W2_2,
                 const float* __restrict__ Wl2,  const float* __restrict__ sc2,
                 float* __restrict__ out, int B) {
    extern __shared__ float S[];
    float* tabS = S;            // 13760 floats
    float* xS   = S + 13760;    // 40960 floats

    const int tid = threadIdx.x;
    const int g   = tid >> 6;        // b-group 0..3
    const int c   = tid & 63;        // channel
    const int b0  = blockIdx.x * NB + g * NBSUB;

    // cooperative copy of the packed table into smem
    {
        const float4* gt4 = (const float4*)g_table;
        float4* tp4 = (float4*)tabS;
#pragma unroll
        for (int k = 0; k < 14; k++) {
            int idx = k * NT + tid;
            if (idx < NROWS * TS / 4) tp4[idx] = gt4[idx];
        }
    }

    // gather x for 4 b's: xS[i*1024 + tid*4 + s]
#pragma unroll
    for (int s = 0; s < NBSUB; s++) {
        int bb = b0 + s; if (bb >= B) bb = B - 1;
        const int base = bb * 64 + c;
        xS[tid * 4 + s] = f0[base];
#pragma unroll
        for (int k = 0; k < 3; k++)
            xS[(1 + k) * 1024 + tid * 4 + s]  = f1[base * 3 + k];
#pragma unroll
        for (int k = 0; k < 9; k++)
            xS[(4 + k) * 1024 + tid * 4 + s]  = f2[base * 9 + k];
#pragma unroll
        for (int k = 0; k < 27; k++)
            xS[(13 + k) * 1024 + tid * 4 + s] = f3[base * 27 + k];
    }
    __syncthreads();

    const char* xtb = (const char*)xS + tid * 16;

    // ---- phase A, pass 1: m0..7  (reads trow[0], trow[1]) ----
    unsigned long long aA[NBSUB][4];
#pragma unroll
    for (int s = 0; s < NBSUB; s++)
#pragma unroll
        for (int k = 0; k < 4; k++) aA[s][k] = 0ull;

    {
        const ulonglong2* trow = (const ulonglong2*)tabS;
        for (int i = 0; i < DIM; i++) {
            const float4 xi = *(const float4*)(xtb + i * XROWB);
            const char* xjp = xtb + i * XROWB;
#pragma unroll 2
            for (int j = i; j < DIM; j++) {
                ulonglong2 q0 = trow[0];
                ulonglong2 q1 = trow[1];
                trow += 4;
                float4 xj = *(const float4*)xjp;
                xjp += XROWB;
                unsigned long long y0 = dup2(xi.x * xj.x);
                unsigned long long y1 = dup2(xi.y * xj.y);
                unsigned long long y2 = dup2(xi.z * xj.z);
                unsigned long long y3 = dup2(xi.w * xj.w);
                fma2(aA[0][0], q0.x, y0); fma2(aA[1][0], q0.x, y1);
                fma2(aA[2][0], q0.x, y2); fma2(aA[3][0], q0.x, y3);
                fma2(aA[0][1], q0.y, y0); fma2(aA[1][1], q0.y, y1);
                fma2(aA[2][1], q0.y, y2); fma2(aA[3][1], q0.y, y3);
                fma2(aA[0][2], q1.x, y0); fma2(aA[1][2], q1.x, y1);
                fma2(aA[2][2], q1.x, y2); fma2(aA[3][2], q1.x, y3);
                fma2(aA[0][3], q1.y, y0); fma2(aA[1][3], q1.y, y1);
                fma2(aA[2][3], q1.y, y2); fma2(aA[3][3], q1.y, y3);
            }
        }
    }

    // ---- phase A, pass 2: m8..12  (reads trow[2], trow[3]) ----
    unsigned long long aB[NBSUB][3];
#pragma unroll
    for (int s = 0; s < NBSUB; s++)
#pragma unroll
        for (int k = 0; k < 3; k++) aB[s][k] = 0ull;

    {
        const ulonglong2* trow = (const ulonglong2*)tabS + 2;
        for (int i = 0; i < DIM; i++) {
            const float4 xi = *(const float4*)(xtb + i * XROWB);
            const char* xjp = xtb + i * XROWB;
#pragma unroll 2
            for (int j = i; j < DIM; j++) {
                ulonglong2 q2 = trow[0];
                ulonglong2 q3 = trow[1];
                trow += 4;
                float4 xj = *(const float4*)xjp;
                xjp += XROWB;
                unsigned long long y0 = dup2(xi.x * xj.x);
                unsigned long long y1 = dup2(xi.y * xj.y);
                unsigned long long y2 = dup2(xi.z * xj.z);
                unsigned long long y3 = dup2(xi.w * xj.w);
                fma2(aB[0][0], q2.x, y0); fma2(aB[1][0], q2.x, y1);
                fma2(aB[2][0], q2.x, y2); fma2(aB[3][0], q2.x, y3);
                fma2(aB[0][1], q2.y, y0); fma2(aB[1][1], q2.y, y1);
                fma2(aB[2][1], q2.y, y2); fma2(aB[3][1], q2.y, y3);
                fma2(aB[0][2], q3.x, y0); fma2(aB[1][2], q3.x, y1);
                fma2(aB[2][2], q3.x, y2); fma2(aB[3][2], q3.x, y3);
            }
        }
    }

    // ---- phase B: a1[s][m] = U1[m,:] . x[s] ----
    unsigned long long a1[NBSUB][7];
#pragma unroll
    for (int s = 0; s < NBSUB; s++)
#pragma unroll
        for (int k = 0; k < 7; k++) a1[s][k] = 0ull;

    {
        const ulonglong2* trow = (const ulonglong2*)tabS + NPAIR * 4;
#pragma unroll 2
        for (int i = 0; i < DIM; i++, trow += 4) {
            ulonglong2 q0 = trow[0];
            ulonglong2 q1 = trow[1];
            ulonglong2 q2 = trow[2];
            ulonglong2 q3 = trow[3];
            float4 xi = *(const float4*)(xtb + i * XROWB);
            unsigned long long y0 = dup2(xi.x);
            unsigned long long y1 = dup2(xi.y);
            unsigned long long y2 = dup2(xi.z);
            unsigned long long y3 = dup2(xi.w);
            fma2(a1[0][0], q0.x, y0); fma2(a1[1][0], q0.x, y1);
            fma2(a1[2][0], q0.x, y2); fma2(a1[3][0], q0.x, y3);
            fma2(a1[0][1], q0.y, y0); fma2(a1[1][1], q0.y, y1);
            fma2(a1[2][1], q0.y, y2); fma2(a1[3][1], q0.y, y3);
            fma2(a1[0][2], q1.x, y0); fma2(a1[1][2], q1.x, y1);
            fma2(a1[2][2], q1.x, y2); fma2(a1[3][2], q1.x, y3);
            fma2(a1[0][3], q1.y, y0); fma2(a1[1][3], q1.y, y1);
            fma2(a1[2][3], q1.y, y2); fma2(a1[3][3], q1.y, y3);
            fma2(a1[0][4], q2.x, y0); fma2(a1[1][4], q2.x, y1);
            fma2(a1[2][4], q2.x, y2); fma2(a1[3][4], q2.x, y3);
            fma2(a1[0][5], q2.y, y0); fma2(a1[1][5], q2.y, y1);
            fma2(a1[2][5], q2.y, y2); fma2(a1[3][5], q2.y, y3);
            fma2(a1[0][6], q3.x, y0); fma2(a1[1][6], q3.x, y1);
            fma2(a1[2][6], q3.x, y2); fma2(a1[3][6], q3.x, y3);
        }
    }

    __syncthreads();   // everyone done reading xS before we overwrite it

    // reuse xS region: Wlin cache + basis20
    float* wlS    = xS;             // 12288 floats
    float* basS20 = xS + 12288;     // 20480 floats

    // Wlin cache: wlS[l*4096 + cc*64 + o]
    {
        const float4* a0p = (const float4*)Wl0;
        const float4* a1p = (const float4*)Wl1;
        const float4* a2p = (const float4*)Wl2;
        float4* w4 = (float4*)wlS;
#pragma unroll
        for (int k = 0; k < 4; k++) {
            int idx = k * NT + tid;
            w4[idx]        = a0p[idx];
            w4[1024 + idx] = a1p[idx];
            w4[2048 + idx] = a2p[idx];
        }
    }

    // fold: basis = a1*w1 + a2*w2, element-aware weights computed here
    const int LSEL[14] = {0, 1, 1, 1, 2, 2, 2, 2, 2, 2, 2, 2, 2, 0};
#pragma unroll
    for (int s = 0; s < NBSUB; s++) {
        int bb = b0 + s; if (bb >= B) bb = B - 1;
        float w10 = 0.f, w11 = 0.f, w12 = 0.f;
        float w20 = 0.f, w21 = 0.f, w22 = 0.f;
#pragma unroll
        for (int e = 0; e < 10; e++) {
            float a = __ldg(&attrs[bb * 10 + e]);
            w10 += a * __ldg(&W1_0[e * 64 + c]);
            w20 += a * __ldg(&W2_0[e * 64 + c]);
            w11 += a * __ldg(&W1_1[e * 64 + c]);
            w21 += a * __ldg(&W2_1[e * 64 + c]);
            w12 += a * __ldg(&W1_2[e * 64 + c]);
            w22 += a * __ldg(&W2_2[e * 64 + c]);
        }
        float w1v[3] = {w10, w11, w12};
        float w2v[3] = {w20, w21, w22};

        float am[14];
#pragma unroll
        for (int k = 0; k < 4; k++) {
            float2 v = unpk2(aA[s][k]);
            am[2 * k] = v.x; am[2 * k + 1] = v.y;
        }
#pragma unroll
        for (int k = 0; k < 3; k++) {
            float2 v = unpk2(aB[s][k]);
            am[8 + 2 * k] = v.x; am[9 + 2 * k] = v.y;
        }
        float a1m[14];
#pragma unroll
        for (int k = 0; k < 7; k++) {
            float2 v = unpk2(a1[s][k]);
            a1m[2 * k] = v.x; a1m[2 * k + 1] = v.y;
        }

        float* b20 = basS20 + ((g * NBSUB + s) * 64 + c) * BSTRIDE;
#pragma unroll
        for (int m = 0; m < 13; m++)
            b20[m] = a1m[m] * w1v[LSEL[m]] + am[m] * w2v[LSEL[m]];
    }
    __syncthreads();

    // ---- self-interaction: r[s][m] = sum_cc basis[b_s][cc][m] * Wlin_l[cc][c] ----
    float r[NBSUB][13];
#pragma unroll
    for (int s = 0; s < NBSUB; s++)
#pragma unroll
        for (int m = 0; m < 13; m++) r[s][m] = 0.0f;

#pragma unroll 2
    for (int cc = 0; cc < 64; cc++) {
        float wv0 = wlS[cc * 64 + c];
        float wv1 = wlS[4096 + cc * 64 + c];
        float wv2 = wlS[8192 + cc * 64 + c];
#pragma unroll
        for (int s = 0; s < NBSUB; s++) {
            const float* br = basS20 + ((g * NBSUB + s) * 64 + cc) * BSTRIDE;
            float4 q0 = *(const float4*)(br);
            float4 q1 = *(const float4*)(br + 4);
            float4 q2 = *(const float4*)(br + 8);
            float b12 = br[12];
            r[s][0]  += q0.x * wv0;
            r[s][1]  += q0.y * wv1;
            r[s][2]  += q0.z * wv1;
            r[s][3]  += q0.w * wv1;
            r[s][4]  += q1.x * wv2;
            r[s][5]  += q1.y * wv2;
            r[s][6]  += q1.z * wv2;
            r[s][7]  += q1.w * wv2;
            r[s][8]  += q2.x * wv2;
            r[s][9]  += q2.y * wv2;
            r[s][10] += q2.z * wv2;
            r[s][11] += q2.w * wv2;
            r[s][12] += b12  * wv2;
        }
    }

    // ---- outputs: concat [out0 (B,C)] [out1 (B,C,3)] [out2 (B,C,9)] ----
    float* o0 = out;
    float* o1 = out + (size_t)B * 64;
    float* o2 = out + (size_t)B * 64 * 4;
#pragma unroll
    for (int s = 0; s < NBSUB; s++) {
        int bb = b0 + s;
        if (bb >= B) break;
        const int bo = bb * 64 + c;
        o0[bo] = r[s][0] + __ldg(&sc0[bo]);
#pragma unroll
        for (int k = 0; k < 3; k++)
            o1[bo * 3 + k] = r[s][1 + k] + __ldg(&sc1[bo * 3 + k]);
#pragma unroll
        for (int k = 0; k < 9; k++)
            o2[bo * 9 + k] = r[s][4 + k] + __ldg(&sc2[bo * 9 + k]);
    }
}

extern "C" void kernel_launch(void* const* d_in, const int* in_sizes, int n_in,
                              void* d_out, int out_size) {
    const float* f0    = (const float*)d_in[0];
    const float* f1    = (const float*)d_in[1];
    const float* f2    = (const float*)d_in[2];
    const float* f3    = (const float*)d_in[3];
    const float* attrs = (const float*)d_in[4];
    const float* U2_0  = (const float*)d_in[5];
    const float* U1_0  = (const float*)d_in[6];
    const float* W1_0  = (const float*)d_in[7];
    const float* W2_0  = (const float*)d_in[8];
    const float* Wl0   = (const float*)d_in[9];
    const float* sc0   = (const float*)d_in[10];
    const float* U2_1  = (const float*)d_in[11];
    const float* U1_1  = (const float*)d_in[12];
    const float* W1_1  = (const float*)d_in[13];
    const float* W2_1  = (const float*)d_in[14];
    const float* Wl1   = (const float*)d_in[15];
    const float* sc1   = (const float*)d_in[16];
    const float* U2_2  = (const float*)d_in[17];
    const float* U1_2  = (const float*)d_in[18];
    const float* W1_2  = (const float*)d_in[19];
    const float* W2_2  = (const float*)d_in[20];
    const float* Wl2   = (const float*)d_in[21];
    const float* sc2   = (const float*)d_in[22];

    const int B = in_sizes[0] / 64;

    cudaFuncSetAttribute(main_kernel,
                         cudaFuncAttributeMaxDynamicSharedMemorySize, SMEM_BYTES);

    prep_kernel<<<(NROWS + 255) / 256, 256>>>(U2_0, U1_0, U2_1, U1_1, U2_2, U1_2);

    const int grid = (B + NB - 1) / NB;
    main_kernel<<<grid, NT, SMEM_BYTES>>>(f0, f1, f2, f3, attrs,
                                          W1_0, W2_0, Wl0, sc0,
                                          W1_1, W2_1, Wl1, sc1,
                                          W1_2, W2_2, Wl2, sc2,
                                          (float*)d_out, B);
}

// round 11
// speedup vs baseline: 2.1598x; 1.4306x over previous
#include <cuda_runtime.h>
#include <stdint.h>

// Problem constants
#define NT    256      // threads per CTA (4 groups x 64 channels)
#define NBSUB 2        // b-values per thread
#define NB    8        // b-values per CTA
#define DIM   40
#define NPAIR 820      // DIM*(DIM+1)/2 unique symmetric pairs
#define NROWS 860      // pairs + 40 U1 rows
#define TS    16       // table row stride (floats)
#define XROWB 2048     // x row stride in bytes (256 threads * 8B)

// Staging table in global, then copied into constant memory.
__device__ float g_table[NROWS * TS];
__constant__ float c_table[NROWS * TS];   // 55 KB of 64 KB budget

__global__ void prep_kernel(const float* __restrict__ U2_0,
                            const float* __restrict__ U1_0,
                            const float* __restrict__ U2_1,
                            const float* __restrict__ U1_1,
                            const float* __restrict__ U2_2,
                            const float* __restrict__ U1_2) {
    int idx = blockIdx.x * blockDim.x + threadIdx.x;
    if (idx >= NROWS) return;
    float row[TS];
#pragma unroll
    for (int k = 0; k < TS; k++) row[k] = 0.0f;

    if (idx < NPAIR) {
        // invert p -> (i, j) for row-major triangular order (i outer, j from i)
        int rem = idx;
        int i = 0;
        while (rem >= DIM - i) { rem -= DIM - i; i++; }
        int j = i + rem;
        const float* U2b[3] = {U2_0, U2_1, U2_2};
#pragma unroll
        for (int m = 0; m < 13; m++) {
            int l  = (m == 0) ? 0 : ((m < 4) ? 1 : 2);
            int mm = (m == 0) ? 0 : ((m < 4) ? (m - 1) : (m - 4));
            const float* U = U2b[l];
            float v = U[(mm * DIM + i) * DIM + j];
            if (i != j) v += U[(mm * DIM + j) * DIM + i];
            row[m] = v;
        }
    } else {
        int i = idx - NPAIR;
        const float* U1b[3] = {U1_0, U1_1, U1_2};
#pragma unroll
        for (int m = 0; m < 13; m++) {
            int l  = (m == 0) ? 0 : ((m < 4) ? 1 : 2);
            int mm = (m == 0) ? 0 : ((m < 4) ? (m - 1) : (m - 4));
            row[m] = U1b[l][mm * DIM + i];
        }
    }
#pragma unroll
    for (int k = 0; k < TS; k++) g_table[idx * TS + k] = row[k];
}

// ---- packed f32x2 helpers ----
__device__ __forceinline__ void fma2(unsigned long long& acc,
                                     unsigned long long u,
                                     unsigned long long y) {
    asm("fma.rn.f32x2 %0, %1, %2, %0;" : "+l"(acc) : "l"(u), "l"(y));
}
__device__ __forceinline__ unsigned long long dup2(float y) {
    unsigned long long r;
    asm("mov.b64 %0, {%1, %1};" : "=l"(r) : "f"(y));
    return r;
}
__device__ __forceinline__ float2 unpk2(unsigned long long v) {
    float2 r;
    asm("mov.b64 {%0, %1}, %2;" : "=f"(r.x), "=f"(r.y) : "l"(v));
    return r;
}
__device__ __forceinline__ unsigned long long pk2(float lo, float hi) {
    unsigned long long r;
    asm("mov.b64 %0, {%1, %2};" : "=l"(r) : "f"(lo), "f"(hi));
    return r;
}

// SMEM layout (floats) — 80 KB per CTA => 2 CTAs/SM:
//   [0, 20480)  xS: x[40][256 threads][2 b]
//               reused after phases: Wlin (12288) + basis[8][64][16] (8192)
#define SMEM_FLOATS 20480
#define SMEM_BYTES  (SMEM_FLOATS * 4)
#define BSTRIDE 16     // basis row stride in floats

__global__ __launch_bounds__(NT, 2)
void main_kernel(const float* __restrict__ f0,  const float* __restrict__ f1,
                 const float* __restrict__ f2,  const float* __restrict__ f3,
                 const float* __restrict__ attrs,
                 const float* __restrict__ W1_0, const float* __restrict__ W2_0,
                 const float* __restrict__ Wl0,  const float* __restrict__ sc0,
                 const float* __restrict__ W1_1, const float* __restrict__ W2_1,
                 const float* __restrict__ Wl1,  const float* __restrict__ sc1,
                 const float* __restrict__ W1_2, const float* __restrict__ W2_2,
                 const float* __restrict__ Wl2,  const float* __restrict__ sc2,
                 float* __restrict__ out, int B) {
    extern __shared__ float S[];
    float* xS = S;   // 20480 floats

    const int tid = threadIdx.x;
    const int g   = tid >> 6;        // b-group 0..3
    const int c   = tid & 63;        // channel
    const int b0  = blockIdx.x * NB + g * NBSUB;

    // gather x for 2 b's: xS[i*512 + tid*2 + s]
#pragma unroll
    for (int s = 0; s < NBSUB; s++) {
        int bb = b0 + s; if (bb >= B) bb = B - 1;
        const int base = bb * 64 + c;
        xS[tid * 2 + s] = f0[base];
#pragma unroll
        for (int k = 0; k < 3; k++)
            xS[(1 + k) * 512 + tid * 2 + s]  = f1[base * 3 + k];
#pragma unroll
        for (int k = 0; k < 9; k++)
            xS[(4 + k) * 512 + tid * 2 + s]  = f2[base * 9 + k];
#pragma unroll
        for (int k = 0; k < 27; k++)
            xS[(13 + k) * 512 + tid * 2 + s] = f3[base * 27 + k];
    }
    __syncthreads();

    const char* xtb = (const char*)xS + tid * 8;

    // ---- phase A: a2[s][m] = sum_{i<=j} u[p][m] * x_i[s] * x_j[s] ----
    // Table rows come from CONSTANT memory (uniform address -> LDC broadcast,
    // separate port, zero smem-crossbar traffic).
    unsigned long long a2[NBSUB][7];
#pragma unroll
    for (int s = 0; s < NBSUB; s++)
#pragma unroll
        for (int k = 0; k < 7; k++) a2[s][k] = 0ull;

    {
        const float* tp = c_table;
        for (int i = 0; i < DIM; i++) {
            const float2 xi = *(const float2*)(xtb + i * XROWB);
            const char* xjp = xtb + i * XROWB;
#pragma unroll 2
            for (int j = i; j < DIM; j++) {
                float4 t0 = *(const float4*)(tp);
                float4 t1 = *(const float4*)(tp + 4);
                float4 t2 = *(const float4*)(tp + 8);
                float  t12 = tp[12];
                tp += TS;
                float2 xj = *(const float2*)xjp;
                xjp += XROWB;
                unsigned long long y0 = dup2(xi.x * xj.x);
                unsigned long long y1 = dup2(xi.y * xj.y);
                unsigned long long u0 = pk2(t0.x, t0.y);
                unsigned long long u1 = pk2(t0.z, t0.w);
                unsigned long long u2 = pk2(t1.x, t1.y);
                unsigned long long u3 = pk2(t1.z, t1.w);
                unsigned long long u4 = pk2(t2.x, t2.y);
                unsigned long long u5 = pk2(t2.z, t2.w);
                unsigned long long u6 = pk2(t12, 0.0f);
                fma2(a2[0][0], u0, y0); fma2(a2[1][0], u0, y1);
                fma2(a2[0][1], u1, y0); fma2(a2[1][1], u1, y1);
                fma2(a2[0][2], u2, y0); fma2(a2[1][2], u2, y1);
                fma2(a2[0][3], u3, y0); fma2(a2[1][3], u3, y1);
                fma2(a2[0][4], u4, y0); fma2(a2[1][4], u4, y1);
                fma2(a2[0][5], u5, y0); fma2(a2[1][5], u5, y1);
                fma2(a2[0][6], u6, y0); fma2(a2[1][6], u6, y1);
            }
        }
    }

    // ---- phase B: a1[s][m] = U1[m,:] . x[s] ----
    unsigned long long a1[NBSUB][7];
#pragma unroll
    for (int s = 0; s < NBSUB; s++)
#pragma unroll
        for (int k = 0; k < 7; k++) a1[s][k] = 0ull;

    {
        const float* tp = c_table + NPAIR * TS;
#pragma unroll 2
        for (int i = 0; i < DIM; i++, tp += TS) {
            float4 t0 = *(const float4*)(tp);
            float4 t1 = *(const float4*)(tp + 4);
            float4 t2 = *(const float4*)(tp + 8);
            float  t12 = tp[12];
            float2 xi = *(const float2*)(xtb + i * XROWB);
            unsigned long long y0 = dup2(xi.x);
            unsigned long long y1 = dup2(xi.y);
            unsigned long long u0 = pk2(t0.x, t0.y);
            unsigned long long u1 = pk2(t0.z, t0.w);
            unsigned long long u2 = pk2(t1.x, t1.y);
            unsigned long long u3 = pk2(t1.z, t1.w);
            unsigned long long u4 = pk2(t2.x, t2.y);
            unsigned long long u5 = pk2(t2.z, t2.w);
            unsigned long long u6 = pk2(t12, 0.0f);
            fma2(a1[0][0], u0, y0); fma2(a1[1][0], u0, y1);
            fma2(a1[0][1], u1, y0); fma2(a1[1][1], u1, y1);
            fma2(a1[0][2], u2, y0); fma2(a1[1][2], u2, y1);
            fma2(a1[0][3], u3, y0); fma2(a1[1][3], u3, y1);
            fma2(a1[0][4], u4, y0); fma2(a1[1][4], u4, y1);
            fma2(a1[0][5], u5, y0); fma2(a1[1][5], u5, y1);
            fma2(a1[0][6], u6, y0); fma2(a1[1][6], u6, y1);
        }
    }

    __syncthreads();   // everyone done reading xS before we overwrite it

    // reuse xS region: Wlin cache + basis16
    float* wlS  = xS;               // 12288 floats
    float* basS = xS + 12288;       // 8192 floats

    // Wlin cache: wlS[l*4096 + cc*64 + o]
    {
        const float4* a0p = (const float4*)Wl0;
        const float4* a1p = (const float4*)Wl1;
        const float4* a2p = (const float4*)Wl2;
        float4* w4 = (float4*)wlS;
#pragma unroll
        for (int k = 0; k < 4; k++) {
            int idx = k * NT + tid;
            w4[idx]        = a0p[idx];
            w4[1024 + idx] = a1p[idx];
            w4[2048 + idx] = a2p[idx];
        }
    }

    // fold: basis = a1*w1 + a2*w2 (element-aware weights computed here)
    const int LSEL[14] = {0, 1, 1, 1, 2, 2, 2, 2, 2, 2, 2, 2, 2, 0};
#pragma unroll
    for (int s = 0; s < NBSUB; s++) {
        int bb = b0 + s; if (bb >= B) bb = B - 1;
        float w10 = 0.f, w11 = 0.f, w12 = 0.f;
        float w20 = 0.f, w21 = 0.f, w22 = 0.f;
#pragma unroll
        for (int e = 0; e < 10; e++) {
            float a = __ldg(&attrs[bb * 10 + e]);
            w10 += a * __ldg(&W1_0[e * 64 + c]);
            w20 += a * __ldg(&W2_0[e * 64 + c]);
            w11 += a * __ldg(&W1_1[e * 64 + c]);
            w21 += a * __ldg(&W2_1[e * 64 + c]);
            w12 += a * __ldg(&W1_2[e * 64 + c]);
            w22 += a * __ldg(&W2_2[e * 64 + c]);
        }
        float w1v[3] = {w10, w11, w12};
        float w2v[3] = {w20, w21, w22};
        float* bs = basS + ((g * NBSUB + s) * 64 + c) * BSTRIDE;
#pragma unroll
        for (int k = 0; k < 7; k++) {
            float2 v2 = unpk2(a2[s][k]);
            float2 v1 = unpk2(a1[s][k]);
            int m0 = 2 * k, m1 = 2 * k + 1;
            bs[m0] = v1.x * w1v[LSEL[m0]] + v2.x * w2v[LSEL[m0]];
            if (m1 < 13)
                bs[m1] = v1.y * w1v[LSEL[m1]] + v2.y * w2v[LSEL[m1]];
        }
    }
    __syncthreads();

    // ---- self-interaction: r[s][m] = sum_cc basis[b_s][cc][m] * Wlin_l[cc][c] ----
    float r[NBSUB][13];
#pragma unroll
    for (int s = 0; s < NBSUB; s++)
#pragma unroll
        for (int m = 0; m < 13; m++) r[s][m] = 0.0f;

#pragma unroll 2
    for (int cc = 0; cc < 64; cc++) {
        float wv0 = wlS[cc * 64 + c];
        float wv1 = wlS[4096 + cc * 64 + c];
        float wv2 = wlS[8192 + cc * 64 + c];
#pragma unroll
        for (int s = 0; s < NBSUB; s++) {
            const float* br = basS + ((g * NBSUB + s) * 64 + cc) * BSTRIDE;
            float4 q0 = *(const float4*)(br);
            float4 q1 = *(const float4*)(br + 4);
            float4 q2 = *(const float4*)(br + 8);
            float b12 = br[12];
            r[s][0]  += q0.x * wv0;
            r[s][1]  += q0.y * wv1;
            r[s][2]  += q0.z * wv1;
            r[s][3]  += q0.w * wv1;
            r[s][4]  += q1.x * wv2;
            r[s][5]  += q1.y * wv2;
            r[s][6]  += q1.z * wv2;
            r[s][7]  += q1.w * wv2;
            r[s][8]  += q2.x * wv2;
            r[s][9]  += q2.y * wv2;
            r[s][10] += q2.z * wv2;
            r[s][11] += q2.w * wv2;
            r[s][12] += b12  * wv2;
        }
    }

    // ---- outputs: concat [out0 (B,C)] [out1 (B,C,3)] [out2 (B,C,9)] ----
    float* o0 = out;
    float* o1 = out + (size_t)B * 64;
    float* o2 = out + (size_t)B * 64 * 4;
#pragma unroll
    for (int s = 0; s < NBSUB; s++) {
        int bb = b0 + s;
        if (bb >= B) break;
        const int bo = bb * 64 + c;
        o0[bo] = r[s][0] + __ldg(&sc0[bo]);
#pragma unroll
        for (int k = 0; k < 3; k++)
            o1[bo * 3 + k] = r[s][1 + k] + __ldg(&sc1[bo * 3 + k]);
#pragma unroll
        for (int k = 0; k < 9; k++)
            o2[bo * 9 + k] = r[s][4 + k] + __ldg(&sc2[bo * 9 + k]);
    }
}

extern "C" void kernel_launch(void* const* d_in, const int* in_sizes, int n_in,
                              void* d_out, int out_size) {
    const float* f0    = (const float*)d_in[0];
    const float* f1    = (const float*)d_in[1];
    const float* f2    = (const float*)d_in[2];
    const float* f3    = (const float*)d_in[3];
    const float* attrs = (const float*)d_in[4];
    const float* U2_0  = (const float*)d_in[5];
    const float* U1_0  = (const float*)d_in[6];
    const float* W1_0  = (const float*)d_in[7];
    const float* W2_0  = (const float*)d_in[8];
    const float* Wl0   = (const float*)d_in[9];
    const float* sc0   = (const float*)d_in[10];
    const float* U2_1  = (const float*)d_in[11];
    const float* U1_1  = (const float*)d_in[12];
    const float* W1_1  = (const float*)d_in[13];
    const float* W2_1  = (const float*)d_in[14];
    const float* Wl1   = (const float*)d_in[15];
    const float* sc1   = (const float*)d_in[16];
    const float* U2_2  = (const float*)d_in[17];
    const float* U1_2  = (const float*)d_in[18];
    const float* W1_2  = (const float*)d_in[19];
    const float* W2_2  = (const float*)d_in[20];
    const float* Wl2   = (const float*)d_in[21];
    const float* sc2   = (const float*)d_in[22];

    const int B = in_sizes[0] / 64;

    cudaFuncSetAttribute(main_kernel,
                         cudaFuncAttributeMaxDynamicSharedMemorySize, SMEM_BYTES);

    prep_kernel<<<(NROWS + 255) / 256, 256>>>(U2_0, U1_0, U2_1, U1_1, U2_2, U1_2);

    // copy staged table into constant memory (graph-capturable D2D memcpy)
    void* src = nullptr;
    void* dst = nullptr;
    cudaGetSymbolAddress(&src, g_table);
    cudaGetSymbolAddress(&dst, c_table);
    cudaMemcpyAsync(dst, src, NROWS * TS * sizeof(float),
                    cudaMemcpyDeviceToDevice, 0);

    const int grid = (B + NB - 1) / NB;
    main_kernel<<<grid, NT, SMEM_BYTES>>>(f0, f1, f2, f3, attrs,
                                          W1_0, W2_0, Wl0, sc0,
                                          W1_1, W2_1, Wl1, sc1,
                                          W1_2, W2_2, Wl2, sc2,
                                          (float*)d_out, B);
}

// round 12
// speedup vs baseline: 2.1965x; 1.0170x over previous
#include <cuda_runtime.h>
#include <stdint.h>

// Problem constants
#define NT    256      // threads per CTA (4 groups x 64 channels)
#define NBSUB 2        // b-values per thread
#define NB    8        // b-values per CTA
#define DIM   40
#define NPAIR 820      // DIM*(DIM+1)/2 unique symmetric pairs
#define NROWS 860      // pairs + 40 U1 rows
#define TS    16       // table row stride (floats)
#define XROWB 2048     // x row stride in bytes (256 threads * 8B)

// Staging table in global, then copied into constant memory.
__device__ float g_table[NROWS * TS];
__constant__ float c_table[NROWS * TS];   // 55 KB of 64 KB budget

__global__ void prep_kernel(const float* __restrict__ U2_0,
                            const float* __restrict__ U1_0,
                            const float* __restrict__ U2_1,
                            const float* __restrict__ U1_1,
                            const float* __restrict__ U2_2,
                            const float* __restrict__ U1_2) {
    int idx = blockIdx.x * blockDim.x + threadIdx.x;
    if (idx >= NROWS) return;
    float row[TS];
#pragma unroll
    for (int k = 0; k < TS; k++) row[k] = 0.0f;

    if (idx < NPAIR) {
        // invert p -> (i, j) for row-major triangular order (i outer, j from i)
        int rem = idx;
        int i = 0;
        while (rem >= DIM - i) { rem -= DIM - i; i++; }
        int j = i + rem;
        const float* U2b[3] = {U2_0, U2_1, U2_2};
#pragma unroll
        for (int m = 0; m < 13; m++) {
            int l  = (m == 0) ? 0 : ((m < 4) ? 1 : 2);
            int mm = (m == 0) ? 0 : ((m < 4) ? (m - 1) : (m - 4));
            const float* U = U2b[l];
            float v = U[(mm * DIM + i) * DIM + j];
            if (i != j) v += U[(mm * DIM + j) * DIM + i];
            row[m] = v;
        }
    } else {
        int i = idx - NPAIR;
        const float* U1b[3] = {U1_0, U1_1, U1_2};
#pragma unroll
        for (int m = 0; m < 13; m++) {
            int l  = (m == 0) ? 0 : ((m < 4) ? 1 : 2);
            int mm = (m == 0) ? 0 : ((m < 4) ? (m - 1) : (m - 4));
            row[m] = U1b[l][mm * DIM + i];
        }
    }
#pragma unroll
    for (int k = 0; k < TS; k++) g_table[idx * TS + k] = row[k];
}

// ---- packed f32x2 helpers ----
__device__ __forceinline__ void fma2(unsigned long long& acc,
                                     unsigned long long u,
                                     unsigned long long y) {
    asm("fma.rn.f32x2 %0, %1, %2, %0;" : "+l"(acc) : "l"(u), "l"(y));
}
__device__ __forceinline__ unsigned long long dup2(float y) {
    unsigned long long r;
    asm("mov.b64 %0, {%1, %1};" : "=l"(r) : "f"(y));
    return r;
}
__device__ __forceinline__ float2 unpk2(unsigned long long v) {
    float2 r;
    asm("mov.b64 {%0, %1}, %2;" : "=f"(r.x), "=f"(r.y) : "l"(v));
    return r;
}

// SMEM layout (floats) — 80 KB per CTA => 2 CTAs/SM:
//   [0, 20480)  xS: x[40][256 threads][2 b]
//               reused after phases: Wlin (12288) + basis[8][64][16] (8192)
#define SMEM_FLOATS 20480
#define SMEM_BYTES  (SMEM_FLOATS * 4)
#define BSTRIDE 16     // basis row stride in floats

__global__ __launch_bounds__(NT, 2)
void main_kernel(const float* __restrict__ f0,  const float* __restrict__ f1,
                 const float* __restrict__ f2,  const float* __restrict__ f3,
                 const float* __restrict__ attrs,
                 const float* __restrict__ W1_0, const float* __restrict__ W2_0,
                 const float* __restrict__ Wl0,  const float* __restrict__ sc0,
                 const float* __restrict__ W1_1, const float* __restrict__ W2_1,
                 const float* __restrict__ Wl1,  const float* __restrict__ sc1,
                 const float* __restrict__ W1_2, const float* __restrict__ W2_2,
                 const float* __restrict__ Wl2,  const float* __restrict__ sc2,
                 float* __restrict__ out, int B) {
    extern __shared__ float S[];
    float* xS = S;   // 20480 floats

    const int tid = threadIdx.x;
    const int g   = tid >> 6;        // b-group 0..3
    const int c   = tid & 63;        // channel
    const int b0  = blockIdx.x * NB + g * NBSUB;

    // gather x for 2 b's: xS[i*512 + tid*2 + s]
#pragma unroll
    for (int s = 0; s < NBSUB; s++) {
        int bb = b0 + s; if (bb >= B) bb = B - 1;
        const int base = bb * 64 + c;
        xS[tid * 2 + s] = f0[base];
#pragma unroll
        for (int k = 0; k < 3; k++)
            xS[(1 + k) * 512 + tid * 2 + s]  = f1[base * 3 + k];
#pragma unroll
        for (int k = 0; k < 9; k++)
            xS[(4 + k) * 512 + tid * 2 + s]  = f2[base * 9 + k];
#pragma unroll
        for (int k = 0; k < 27; k++)
            xS[(13 + k) * 512 + tid * 2 + s] = f3[base * 27 + k];
    }
    __syncthreads();

    const char* xtb = (const char*)xS + tid * 8;

    // ---- phase A: a2[s][m] = sum_{i<=j} u[p][m] * x_i[s] * x_j[s] ----
    // Table rows from CONSTANT memory, loaded as 64/128-bit words so the
    // coefficient pairs land directly in aligned register pairs for FFMA2
    // (no repacking movs).
    unsigned long long a2[NBSUB][7];
#pragma unroll
    for (int s = 0; s < NBSUB; s++)
#pragma unroll
        for (int k = 0; k < 7; k++) a2[s][k] = 0ull;

    {
        const ulonglong2* trow = (const ulonglong2*)c_table;
        for (int i = 0; i < DIM; i++) {
            const float2 xi = *(const float2*)(xtb + i * XROWB);
            const char* xjp = xtb + i * XROWB;
#pragma unroll 2
            for (int j = i; j < DIM; j++) {
                ulonglong2 q0 = trow[0];
                ulonglong2 q1 = trow[1];
                ulonglong2 q2 = trow[2];
                unsigned long long q3 = ((const unsigned long long*)trow)[6];
                trow += 4;
                float2 xj = *(const float2*)xjp;
                xjp += XROWB;
                unsigned long long y0 = dup2(xi.x * xj.x);
                unsigned long long y1 = dup2(xi.y * xj.y);
                fma2(a2[0][0], q0.x, y0); fma2(a2[1][0], q0.x, y1);
                fma2(a2[0][1], q0.y, y0); fma2(a2[1][1], q0.y, y1);
                fma2(a2[0][2], q1.x, y0); fma2(a2[1][2], q1.x, y1);
                fma2(a2[0][3], q1.y, y0); fma2(a2[1][3], q1.y, y1);
                fma2(a2[0][4], q2.x, y0); fma2(a2[1][4], q2.x, y1);
                fma2(a2[0][5], q2.y, y0); fma2(a2[1][5], q2.y, y1);
                fma2(a2[0][6], q3,   y0); fma2(a2[1][6], q3,   y1);
            }
        }
    }

    // ---- phase B: a1[s][m] = U1[m,:] . x[s] ----
    unsigned long long a1[NBSUB][7];
#pragma unroll
    for (int s = 0; s < NBSUB; s++)
#pragma unroll
        for (int k = 0; k < 7; k++) a1[s][k] = 0ull;

    {
        const ulonglong2* trow = (const ulonglong2*)c_table + NPAIR * 4;
#pragma unroll 2
        for (int i = 0; i < DIM; i++, trow += 4) {
            ulonglong2 q0 = trow[0];
            ulonglong2 q1 = trow[1];
            ulonglong2 q2 = trow[2];
            unsigned long long q3 = ((const unsigned long long*)trow)[6];
            float2 xi = *(const float2*)(xtb + i * XROWB);
            unsigned long long y0 = dup2(xi.x);
            unsigned long long y1 = dup2(xi.y);
            fma2(a1[0][0], q0.x, y0); fma2(a1[1][0], q0.x, y1);
            fma2(a1[0][1], q0.y, y0); fma2(a1[1][1], q0.y, y1);
            fma2(a1[0][2], q1.x, y0); fma2(a1[1][2], q1.x, y1);
            fma2(a1[0][3], q1.y, y0); fma2(a1[1][3], q1.y, y1);
            fma2(a1[0][4], q2.x, y0); fma2(a1[1][4], q2.x, y1);
            fma2(a1[0][5], q2.y, y0); fma2(a1[1][5], q2.y, y1);
            fma2(a1[0][6], q3,   y0); fma2(a1[1][6], q3,   y1);
        }
    }

    __syncthreads();   // everyone done reading xS before we overwrite it

    // reuse xS region: Wlin cache + basis16
    float* wlS  = xS;               // 12288 floats
    float* basS = xS + 12288;       // 8192 floats

    // Wlin cache: wlS[l*4096 + cc*64 + o]
    {
        const float4* a0p = (const float4*)Wl0;
        const float4* a1p = (const float4*)Wl1;
        const float4* a2p = (const float4*)Wl2;
        float4* w4 = (float4*)wlS;
#pragma unroll
        for (int k = 0; k < 4; k++) {
            int idx = k * NT + tid;
            w4[idx]        = a0p[idx];
            w4[1024 + idx] = a1p[idx];
            w4[2048 + idx] = a2p[idx];
        }
    }

    // fold: basis = a1*w1 + a2*w2 (element-aware weights computed here)
    const int LSEL[14] = {0, 1, 1, 1, 2, 2, 2, 2, 2, 2, 2, 2, 2, 0};
#pragma unroll
    for (int s = 0; s < NBSUB; s++) {
        int bb = b0 + s; if (bb >= B) bb = B - 1;
        float w10 = 0.f, w11 = 0.f, w12 = 0.f;
        float w20 = 0.f, w21 = 0.f, w22 = 0.f;
#pragma unroll
        for (int e = 0; e < 10; e++) {
            float a = __ldg(&attrs[bb * 10 + e]);
            w10 += a * __ldg(&W1_0[e * 64 + c]);
            w20 += a * __ldg(&W2_0[e * 64 + c]);
            w11 += a * __ldg(&W1_1[e * 64 + c]);
            w21 += a * __ldg(&W2_1[e * 64 + c]);
            w12 += a * __ldg(&W1_2[e * 64 + c]);
            w22 += a * __ldg(&W2_2[e * 64 + c]);
        }
        float w1v[3] = {w10, w11, w12};
        float w2v[3] = {w20, w21, w22};
        float* bs = basS + ((g * NBSUB + s) * 64 + c) * BSTRIDE;
#pragma unroll
        for (int k = 0; k < 7; k++) {
            float2 v2 = unpk2(a2[s][k]);
            float2 v1 = unpk2(a1[s][k]);
            int m0 = 2 * k, m1 = 2 * k + 1;
            bs[m0] = v1.x * w1v[LSEL[m0]] + v2.x * w2v[LSEL[m0]];
            if (m1 < 13)
                bs[m1] = v1.y * w1v[LSEL[m1]] + v2.y * w2v[LSEL[m1]];
        }
    }
    __syncthreads();

    // ---- self-interaction: r[s][m] = sum_cc basis[b_s][cc][m] * Wlin_l[cc][c] ----
    float r[NBSUB][13];
#pragma unroll
    for (int s = 0; s < NBSUB; s++)
#pragma unroll
        for (int m = 0; m < 13; m++) r[s][m] = 0.0f;

#pragma unroll 2
    for (int cc = 0; cc < 64; cc++) {
        float wv0 = wlS[cc * 64 + c];
        float wv1 = wlS[4096 + cc * 64 + c];
        float wv2 = wlS[8192 + cc * 64 + c];
#pragma unroll
        for (int s = 0; s < NBSUB; s++) {
            const float* br = basS + ((g * NBSUB + s) * 64 + cc) * BSTRIDE;
            float4 q0 = *(const float4*)(br);
            float4 q1 = *(const float4*)(br + 4);
            float4 q2 = *(const float4*)(br + 8);
            float b12 = br[12];
            r[s][0]  += q0.x * wv0;
            r[s][1]  += q0.y * wv1;
            r[s][2]  += q0.z * wv1;
            r[s][3]  += q0.w * wv1;
            r[s][4]  += q1.x * wv2;
            r[s][5]  += q1.y * wv2;
            r[s][6]  += q1.z * wv2;
            r[s][7]  += q1.w * wv2;
            r[s][8]  += q2.x * wv2;
            r[s][9]  += q2.y * wv2;
            r[s][10] += q2.z * wv2;
            r[s][11] += q2.w * wv2;
            r[s][12] += b12  * wv2;
        }
    }

    // ---- outputs: concat [out0 (B,C)] [out1 (B,C,3)] [out2 (B,C,9)] ----
    float* o0 = out;
    float* o1 = out + (size_t)B * 64;
    float* o2 = out + (size_t)B * 64 * 4;
#pragma unroll
    for (int s = 0; s < NBSUB; s++) {
        int bb = b0 + s;
        if (bb >= B) break;
        const int bo = bb * 64 + c;
        o0[bo] = r[s][0] + __ldg(&sc0[bo]);
#pragma unroll
        for (int k = 0; k < 3; k++)
            o1[bo * 3 + k] = r[s][1 + k] + __ldg(&sc1[bo * 3 + k]);
#pragma unroll
        for (int k = 0; k < 9; k++)
            o2[bo * 9 + k] = r[s][4 + k] + __ldg(&sc2[bo * 9 + k]);
    }
}

extern "C" void kernel_launch(void* const* d_in, const int* in_sizes, int n_in,
                              void* d_out, int out_size) {
    const float* f0    = (const float*)d_in[0];
    const float* f1    = (const float*)d_in[1];
    const float* f2    = (const float*)d_in[2];
    const float* f3    = (const float*)d_in[3];
    const float* attrs = (const float*)d_in[4];
    const float* U2_0  = (const float*)d_in[5];
    const float* U1_0  = (const float*)d_in[6];
    const float* W1_0  = (const float*)d_in[7];
    const float* W2_0  = (const float*)d_in[8];
    const float* Wl0   = (const float*)d_in[9];
    const float* sc0   = (const float*)d_in[10];
    const float* U2_1  = (const float*)d_in[11];
    const float* U1_1  = (const float*)d_in[12];
    const float* W1_1  = (const float*)d_in[13];
    const float* W2_1  = (const float*)d_in[14];
    const float* Wl1   = (const float*)d_in[15];
    const float* sc1   = (const float*)d_in[16];
    const float* U2_2  = (const float*)d_in[17];
    const float* U1_2  = (const float*)d_in[18];
    const float* W1_2  = (const float*)d_in[19];
    const float* W2_2  = (const float*)d_in[20];
    const float* Wl2   = (const float*)d_in[21];
    const float* sc2   = (const float*)d_in[22];

    const int B = in_sizes[0] / 64;

    cudaFuncSetAttribute(main_kernel,
                         cudaFuncAttributeMaxDynamicSharedMemorySize, SMEM_BYTES);

    prep_kernel<<<(NROWS + 255) / 256, 256>>>(U2_0, U1_0, U2_1, U1_1, U2_2, U1_2);

    // copy staged table into constant memory (graph-capturable D2D memcpy)
    void* src = nullptr;
    void* dst = nullptr;
    cudaGetSymbolAddress(&src, g_table);
    cudaGetSymbolAddress(&dst, c_table);
    cudaMemcpyAsync(dst, src, NROWS * TS * sizeof(float),
                    cudaMemcpyDeviceToDevice, 0);

    const int grid = (B + NB - 1) / NB;
    main_kernel<<<grid, NT, SMEM_BYTES>>>(f0, f1, f2, f3, attrs,
                                          W1_0, W2_0, Wl0, sc0,
                                          W1_1, W2_1, Wl1, sc1,
                                          W1_2, W2_2, Wl2, sc2,
                                          (float*)d_out, B);
}